// round 10
// baseline (speedup 1.0000x reference)
#include <cuda_runtime.h>

#define BB 16
#define DD 768
#define LL 96
#define CHUNK 128
#define NCHUNK 6
#define XPITCH 132   // 128 + 4 pad (bank-conflict-free staging)
#define SOFT_ELEMS (BB*LL*LL*DD)        // 113246208
#define HW_ELEMS   (BB*LL*LL*3)         // 442368
#define SPAN_SMEM_FLOATS (LL*XPITCH + LL + 192)

__constant__ float c_posw[6] = {2.0f, 1.5f, 1.0f, 0.8f, 0.3f, 0.5f};
__constant__ float c_depw[6] = {2.0f, 1.5f, 1.5f, 1.2f, 1.0f, 0.5f};

__device__ float g_E[BB*LL];     // exp(base/TEMP) per token
__device__ float g_S[BB*DD];     // per-(b,d) column sum of embeds

// ---------------------------------------------------------------------------
// prep: warp-per-d column sums; block x==0 writes g_E; blocks x<48 also emit
// the top-3 aux outputs (hw/hi) for 4 chains each, lane-parallel over spans.
// grid (96, 16), block 256.
// ---------------------------------------------------------------------------
__global__ void prep_kernel(const float* __restrict__ x, const int* __restrict__ par,
                            const int* __restrict__ pos, const int* __restrict__ dep,
                            float* __restrict__ out, int write_aux) {
    int b = blockIdx.y;
    int tid = threadIdx.x;
    int w = tid >> 5, lane = tid & 31;
    int d = blockIdx.x * 8 + w;

    const float* p = x + ((size_t)b*DD + d)*LL;
    float s = p[lane] + p[lane + 32] + p[lane + 64];
#pragma unroll
    for (int off = 16; off; off >>= 1) s += __shfl_down_sync(0xffffffffu, s, off);
    if (lane == 0) g_S[b*DD + d] = s;

    if (blockIdx.x >= 48) return;

    // ---- local E/base/tables for aux work ----
    __shared__ float sE[LL], sB[LL], sM2[192], sMm[192];
    __shared__ int cnt[LL];
    if (tid < LL) cnt[tid] = 0;
    __syncthreads();
    if (tid < LL) atomicAdd(&cnt[par[b*LL + tid]], 1);
    for (int k = tid; k < 191; k += 256) {
        float denom = __fadd_rn(1.0f, 0.5f*(float)k);   // exact
        float med = __fdiv_rn(0.5f, denom);             // JAX medoid bits
        sMm[k] = med;
        sM2[k] = expf(med / 0.7f);
    }
    __syncthreads();
    if (tid < LL) {
        // XLA elementwise, no fma contraction
        float t0 = __fmul_rn(1.5f, (float)cnt[tid]);
        float t1 = __fadd_rn(2.0f, t0);
        float t2 = __fadd_rn(t1, __fmul_rn(0.8f, c_posw[pos[b*LL + tid]]));
        float base = __fadd_rn(t2, __fmul_rn(0.5f, c_depw[dep[b*LL + tid]]));
        sB[tid] = base;
        float e = expf(base / 0.7f);
        sE[tid] = e;
        if (blockIdx.x == 0) g_E[b*LL + tid] = e;
    }
    __syncthreads();

    if (!write_aux) return;

    // ---- aux: chain c2 = blockIdx.x + 48*w (w in [0,8) -> covers [0,192)) ----
    int c2 = blockIdx.x + 48*w;
    if (c2 > 190) return;
    int l0 = c2 >> 1;
    int r0 = c2 - l0;
    int n = min(l0, (LL-1) - r0) + 1;

    float* hw_base = out + SOFT_ELEMS;
    float* hi_base = out + SOFT_ELEMS + HW_ELEMS;

    for (int j = lane; j < n; j += 32) {
        int l = l0 - j, r = r0 + j;
        float za = 0.f;
        float y0 = -1e30f, y1 = -1e30f, y2 = -1e30f;
        int   i0 = 0x7fffffff, i1 = 0x7fffffff, i2 = 0x7fffffff;
        for (int t = l; t <= r; ++t) {
            int k = 2*t - c2; k = k < 0 ? -k : k;
            float wt = sE[t] * sM2[k];
            float y = __fadd_rn(sB[t], sMm[k]);   // JAX score bits (order key)
            bool q0 = (y > y0) || (y == y0 && t < i0);
            bool q1 = (y > y1) || (y == y1 && t < i1);
            bool q2 = (y > y2) || (y == y2 && t < i2);
            if (q0)      { y2=y1; i2=i1; y1=y0; i1=i0; y0=y; i0=t; }
            else if (q1) { y2=y1; i2=i1; y1=y; i1=t; }
            else if (q2) { y2=y;  i2=t; }
            za += wt - 1.0f;
        }
        float invZ = __fdividef(1.0f, (float)LL + za);
        int len = r - l + 1;
        int k0 = 2*i0 - c2; k0 = k0 < 0 ? -k0 : k0;
        float w0 = sE[i0] * sM2[k0];
        float hv1, hv2, fi1, fi2;
        if (len >= 3) {
            int k1 = 2*i1 - c2; k1 = k1 < 0 ? -k1 : k1;
            int k2v = 2*i2 - c2; k2v = k2v < 0 ? -k2v : k2v;
            hv1 = sE[i1]*sM2[k1]*invZ;  fi1 = (float)i1;
            hv2 = sE[i2]*sM2[k2v]*invZ; fi2 = (float)i2;
        } else if (len == 2) {
            int k1 = 2*i1 - c2; k1 = k1 < 0 ? -k1 : k1;
            hv1 = sE[i1]*sM2[k1]*invZ;  fi1 = (float)i1;
            hv2 = invZ;                 fi2 = (l > 0) ? 0.f : (float)(r+1);
        } else {
            hv1 = invZ; hv2 = invZ;
            if (l == 0)      { fi1 = 1.f; fi2 = 2.f; }
            else if (l == 1) { fi1 = 0.f; fi2 = 2.f; }
            else             { fi1 = 0.f; fi2 = 1.f; }
        }
        size_t row = (size_t)(b*LL + l)*LL + r;
        float* hw = hw_base + row*3;
        float* hi = hi_base + row*3;
        hw[0] = w0*invZ; hw[1] = hv1; hw[2] = hv2;
        hi[0] = (float)i0; hi[1] = fi1; hi[2] = fi2;
    }
}

// ---------------------------------------------------------------------------
// lean per-warp center-chain walker (soft_heads only)
// ---------------------------------------------------------------------------
__device__ __forceinline__ void run_chain(
    const float* __restrict__ x_sm, const float* __restrict__ E_sm,
    const float* __restrict__ M2,
    float* __restrict__ out, int b, int c2, int chunk, int lane)
{
    const int dlo = (lane << 2);
    const float* Sp = g_S + b*DD + chunk*CHUNK + dlo;
    float4 Sa = *(const float4*)Sp;

    int l = c2 >> 1;
    int r = c2 - l;
    int kl = c2 - 2*l;   // 0 or 1
    int kr = 2*r - c2;   // 0 or 1

    const float* xl = x_sm + l*XPITCH + dlo;
    const float* xr = x_sm + r*XPITCH + dlo;

    float4 A = make_float4(0.f,0.f,0.f,0.f);
    float za = 0.f;

    auto addtok = [&](int t, int k, const float* xrow) {
        float a = E_sm[t] * M2[k] - 1.0f;
        za += a;
        float4 xa = *(const float4*)xrow;
        A.x += a*xa.x; A.y += a*xa.y; A.z += a*xa.z; A.w += a*xa.w;
    };

    addtok(l, kl, xl);
    if (r != l) addtok(r, kr, xr);

    float* o = out + ((size_t)((b*LL + l)*LL + r))*DD + chunk*CHUNK + dlo;
    const ptrdiff_t ODELTA = -(ptrdiff_t)(LL-1)*DD;

    while (1) {
        float invZ = __fdividef(1.0f, (float)LL + za);
        float4 o0;
        o0.x = (A.x + Sa.x)*invZ; o0.y = (A.y + Sa.y)*invZ;
        o0.z = (A.z + Sa.z)*invZ; o0.w = (A.w + Sa.w)*invZ;
        __stcs((float4*)o, o0);

        if (l == 0 || r == LL-1) break;
        --l; ++r; kl += 2; kr += 2;
        xl -= XPITCH; xr += XPITCH;
        addtok(l, kl, xl);
        addtok(r, kr, xr);
        o += ODELTA;
    }
}

// ---------------------------------------------------------------------------
// span kernel: grid (6, 8, 16), block 512, 3 CTAs/SM (48 warps = 75% ceiling)
//   yb in [0,6): span chains for d-chunk yb; warp u = g*16+wid owns {u, 96+u}
//   yb in {6,7}: zero-fill CTAs, unit z = (yb-6)*6+g in [0,12),
//                balanced row pairs (m, 95-m), m = z, z+12, z+24, z+36
// ---------------------------------------------------------------------------
__global__ void __launch_bounds__(512, 3)
span_kernel(const float* __restrict__ x, float* __restrict__ out, int write_aux) {
    int g = blockIdx.x, yb = blockIdx.y, b = blockIdx.z;
    int tid = threadIdx.x;

    if (yb >= NCHUNK) {
        int z = (yb - NCHUNK)*6 + g;   // [0,12)
        float4 zz = make_float4(0.f, 0.f, 0.f, 0.f);
        for (int m = z; m < 48; m += 12) {
#pragma unroll
            for (int side = 0; side < 2; side++) {
                int l = side ? (LL-1 - m) : m;
                if (l == 0) continue;
                float4* p = (float4*)(out + (size_t)(b*LL + l)*LL*DD);
                int n4 = l * (DD/4);
                for (int i = tid; i < n4; i += 512) __stcs(p + i, zz);
                if (write_aux) {
                    float* hw = out + SOFT_ELEMS + (size_t)(b*LL + l)*LL*3;
                    float* hi = hw + HW_ELEMS;
                    int n = l*3;
                    for (int i = tid; i < n; i += 512) hw[i] = 0.f;
                    for (int i = tid; i < n; i += 512) hi[i] = -1.f;
                }
            }
        }
        return;
    }

    int chunk = yb;
    extern __shared__ float sm[];
    float* x_sm = sm;                 // [96][132]
    float* E_sm = sm + LL*XPITCH;     // [96]
    float* M2   = E_sm + LL;          // [192]

    const float* gx = x + ((size_t)b*DD + (size_t)chunk*CHUNK)*LL;
    for (int i = tid; i < CHUNK*LL; i += 512) {
        int d = i / LL;
        int t = i - d*LL;
        x_sm[t*XPITCH + d] = gx[i];
    }
    for (int k = tid; k < 191; k += 512) {
        float denom = __fadd_rn(1.0f, 0.5f*(float)k);
        M2[k] = expf(__fdiv_rn(0.5f, denom) / 0.7f);
    }
    if (tid < LL) E_sm[tid] = g_E[b*LL + tid];
    __syncthreads();

    int wid = tid >> 5, lane = tid & 31;
    int u = g*16 + wid;                     // [0,96)

    run_chain(x_sm, E_sm, M2, out, b, u, chunk, lane);
    if (u < 95)
        run_chain(x_sm, E_sm, M2, out, b, 96 + u, chunk, lane);
}

// ---------------------------------------------------------------------------
extern "C" void kernel_launch(void* const* d_in, const int* in_sizes, int n_in,
                              void* d_out, int out_size) {
    const float* x  = (const float*)d_in[0];
    const int* par  = (const int*)d_in[1];
    const int* pos  = (const int*)d_in[2];
    const int* dep  = (const int*)d_in[3];
    float* out = (float*)d_out;

    int write_aux = (out_size >= SOFT_ELEMS + 2*HW_ELEMS) ? 1 : 0;

    prep_kernel<<<dim3(96, BB), 256>>>(x, par, pos, dep, out, write_aux);

    int smem = SPAN_SMEM_FLOATS * 4;
    cudaFuncSetAttribute(span_kernel, cudaFuncAttributeMaxDynamicSharedMemorySize, smem);
    span_kernel<<<dim3(6, NCHUNK + 2, BB), 512, smem>>>(x, out, write_aux);
}

// round 11
// speedup vs baseline: 1.2398x; 1.2398x over previous
#include <cuda_runtime.h>

#define BB 16
#define DD 768
#define LL 96
#define CHUNK 128
#define NCHUNK 6
#define XPITCH 132   // 128 + 4 pad (bank-conflict-free staging)
#define SOFT_ELEMS (BB*LL*LL*DD)        // 113246208
#define HW_ELEMS   (BB*LL*LL*3)         // 442368
#define SPAN_SMEM_FLOATS (LL*XPITCH + LL + 192)

__constant__ float c_posw[6] = {2.0f, 1.5f, 1.0f, 0.8f, 0.3f, 0.5f};
__constant__ float c_depw[6] = {2.0f, 1.5f, 1.5f, 1.2f, 1.0f, 0.5f};

__device__ float g_E[BB*LL];     // exp(base/TEMP) per token
__device__ float g_base[BB*LL];  // raw base score bits (XLA mul/add path)
__device__ float g_S[BB*DD];     // per-(b,d) column sum of embeds

// ---------------------------------------------------------------------------
// prep (fast): warp-per-d column sums; block x==0 also does degree/E/base
// grid (96, 16), block 256  (~4-5 us)
// ---------------------------------------------------------------------------
__global__ void prep_kernel(const float* __restrict__ x, const int* __restrict__ par,
                            const int* __restrict__ pos, const int* __restrict__ dep) {
    int b = blockIdx.y;
    int tid = threadIdx.x;
    int w = tid >> 5, lane = tid & 31;
    int d = blockIdx.x * 8 + w;

    const float* p = x + ((size_t)b*DD + d)*LL;
    float s = p[lane] + p[lane + 32] + p[lane + 64];
#pragma unroll
    for (int off = 16; off; off >>= 1) s += __shfl_down_sync(0xffffffffu, s, off);
    if (lane == 0) g_S[b*DD + d] = s;

    if (blockIdx.x == 0) {
        __shared__ int cnt[LL];
        if (tid < LL) cnt[tid] = 0;
        __syncthreads();
        if (tid < LL) atomicAdd(&cnt[par[b*LL + tid]], 1);
        __syncthreads();
        if (tid < LL) {
            // XLA elementwise, no fma contraction
            float t0 = __fmul_rn(1.5f, (float)cnt[tid]);
            float t1 = __fadd_rn(2.0f, t0);
            float t2 = __fadd_rn(t1, __fmul_rn(0.8f, c_posw[pos[b*LL + tid]]));
            float base = __fadd_rn(t2, __fmul_rn(0.5f, c_depw[dep[b*LL + tid]]));
            g_base[b*LL + tid] = base;
            g_E[b*LL + tid] = expf(base / 0.7f);
        }
    }
}

// ---------------------------------------------------------------------------
// lean per-warp center-chain walker (soft_heads only)
// ---------------------------------------------------------------------------
__device__ __forceinline__ void run_chain(
    const float* __restrict__ x_sm, const float* __restrict__ E_sm,
    const float* __restrict__ M2,
    float* __restrict__ out, int b, int c2, int chunk, int lane)
{
    const int dlo = (lane << 2);
    const float* Sp = g_S + b*DD + chunk*CHUNK + dlo;
    float4 Sa = *(const float4*)Sp;

    int l = c2 >> 1;
    int r = c2 - l;
    int kl = c2 - 2*l;   // 0 or 1
    int kr = 2*r - c2;   // 0 or 1

    const float* xl = x_sm + l*XPITCH + dlo;
    const float* xr = x_sm + r*XPITCH + dlo;

    float4 A = make_float4(0.f,0.f,0.f,0.f);
    float za = 0.f;

    auto addtok = [&](int t, int k, const float* xrow) {
        float a = E_sm[t] * M2[k] - 1.0f;
        za += a;
        float4 xa = *(const float4*)xrow;
        A.x += a*xa.x; A.y += a*xa.y; A.z += a*xa.z; A.w += a*xa.w;
    };

    addtok(l, kl, xl);
    if (r != l) addtok(r, kr, xr);

    float* o = out + ((size_t)((b*LL + l)*LL + r))*DD + chunk*CHUNK + dlo;
    const ptrdiff_t ODELTA = -(ptrdiff_t)(LL-1)*DD;

    while (1) {
        float invZ = __fdividef(1.0f, (float)LL + za);
        float4 o0;
        o0.x = (A.x + Sa.x)*invZ; o0.y = (A.y + Sa.y)*invZ;
        o0.z = (A.z + Sa.z)*invZ; o0.w = (A.w + Sa.w)*invZ;
        __stcs((float4*)o, o0);

        if (l == 0 || r == LL-1) break;
        --l; ++r; kl += 2; kr += 2;
        xl -= XPITCH; xr += XPITCH;
        addtok(l, kl, xl);
        addtok(r, kr, xr);
        o += ODELTA;
    }
}

// ---------------------------------------------------------------------------
// aux chain walker: incremental top-3 + Z only; lane 0 emits hw/hi per span.
// All lanes compute redundantly (warp-uniform); no x reads, no big stores.
// ---------------------------------------------------------------------------
__device__ void run_aux_chain(
    const float* __restrict__ E_sm, const float* __restrict__ base_sm,
    const float* __restrict__ M2, const float* __restrict__ Mm,
    float* __restrict__ out, int b, int c2, int lane)
{
    int l = c2 >> 1;
    int r = c2 - l;
    int kl = c2 - 2*l;
    int kr = 2*r - c2;

    float za = 0.f;
    float y0 = -1e30f, y1 = -1e30f, y2 = -1e30f;
    int   i0 = 0x7fffffff, i1 = 0x7fffffff, i2 = 0x7fffffff;

    auto addtok = [&](int t, int k) {
        za += E_sm[t] * M2[k] - 1.0f;
        float y = __fadd_rn(base_sm[t], Mm[k]);   // JAX score bits (order key)
        bool q0 = (y > y0) || (y == y0 && t < i0);
        bool q1 = (y > y1) || (y == y1 && t < i1);
        bool q2 = (y > y2) || (y == y2 && t < i2);
        if (q0)      { y2=y1; i2=i1; y1=y0; i1=i0; y0=y; i0=t; }
        else if (q1) { y2=y1; i2=i1; y1=y; i1=t; }
        else if (q2) { y2=y;  i2=t; }
    };

    addtok(l, kl);
    if (r != l) addtok(r, kr);

    float* hw = out + SOFT_ELEMS + (size_t)((b*LL + l)*LL + r)*3;
    float* hi = hw + HW_ELEMS;
    const ptrdiff_t HDELTA = -(ptrdiff_t)(LL-1)*3;

    while (1) {
        if (lane == 0) {
            float invZ = __fdividef(1.0f, (float)LL + za);
            int len = r - l + 1;
            int k0 = 2*i0 - c2; k0 = k0 < 0 ? -k0 : k0;
            float w0 = E_sm[i0] * M2[k0];
            float hv1, hv2, fi1, fi2;
            if (len >= 3) {
                int k1 = 2*i1 - c2; k1 = k1 < 0 ? -k1 : k1;
                int k2v = 2*i2 - c2; k2v = k2v < 0 ? -k2v : k2v;
                hv1 = E_sm[i1]*M2[k1]*invZ;  fi1 = (float)i1;
                hv2 = E_sm[i2]*M2[k2v]*invZ; fi2 = (float)i2;
            } else if (len == 2) {
                int k1 = 2*i1 - c2; k1 = k1 < 0 ? -k1 : k1;
                hv1 = E_sm[i1]*M2[k1]*invZ;  fi1 = (float)i1;
                hv2 = invZ;                  fi2 = (l > 0) ? 0.f : (float)(r+1);
            } else {
                hv1 = invZ; hv2 = invZ;
                if (l == 0)      { fi1 = 1.f; fi2 = 2.f; }
                else if (l == 1) { fi1 = 0.f; fi2 = 2.f; }
                else             { fi1 = 0.f; fi2 = 1.f; }
            }
            hw[0] = w0*invZ; hw[1] = hv1; hw[2] = hv2;
            hi[0] = (float)i0; hi[1] = fi1; hi[2] = fi2;
        }
        if (l == 0 || r == LL-1) break;
        --l; ++r; kl += 2; kr += 2;
        addtok(l, kl);
        addtok(r, kr);
        hw += HDELTA; hi += HDELTA;
    }
}

// ---------------------------------------------------------------------------
// span kernel: grid (6, 9, 16), block 512, 3 CTAs/SM
//   yb in [0,6): span chains for d-chunk yb; warp u = g*16+wid owns {u, 96+u}
//   yb in {6,7}: zero-fill CTAs, unit z = (yb-6)*6+g in [0,12),
//                balanced row pairs (m, 95-m), m = z, z+12, z+24, z+36
//   yb == 8   : aux CTAs — warp u walks chain pair {u, 96+u}, emits hw/hi
// ---------------------------------------------------------------------------
__global__ void __launch_bounds__(512, 3)
span_kernel(const float* __restrict__ x, float* __restrict__ out, int write_aux) {
    int g = blockIdx.x, yb = blockIdx.y, b = blockIdx.z;
    int tid = threadIdx.x;

    if (yb == NCHUNK + 2) {
        // ---- aux slice ----
        if (!write_aux) return;
        __shared__ float sE[LL], sB[LL], sM2[192], sMm[192];
        for (int k = tid; k < 191; k += 512) {
            float denom = __fadd_rn(1.0f, 0.5f*(float)k);   // exact
            float med = __fdiv_rn(0.5f, denom);             // JAX medoid bits
            sMm[k] = med;
            sM2[k] = expf(med / 0.7f);
        }
        if (tid < LL) {
            sE[tid] = g_E[b*LL + tid];
            sB[tid] = g_base[b*LL + tid];
        }
        __syncthreads();
        int wid = tid >> 5, lane = tid & 31;
        int u = g*16 + wid;                 // [0,96)
        run_aux_chain(sE, sB, sM2, sMm, out, b, u, lane);
        if (u < 95)
            run_aux_chain(sE, sB, sM2, sMm, out, b, 96 + u, lane);
        return;
    }

    if (yb >= NCHUNK) {
        // ---- zero-fill ----
        int z = (yb - NCHUNK)*6 + g;   // [0,12)
        float4 zz = make_float4(0.f, 0.f, 0.f, 0.f);
        for (int m = z; m < 48; m += 12) {
#pragma unroll
            for (int side = 0; side < 2; side++) {
                int l = side ? (LL-1 - m) : m;
                if (l == 0) continue;
                float4* p = (float4*)(out + (size_t)(b*LL + l)*LL*DD);
                int n4 = l * (DD/4);
                for (int i = tid; i < n4; i += 512) __stcs(p + i, zz);
                if (write_aux) {
                    float* hw = out + SOFT_ELEMS + (size_t)(b*LL + l)*LL*3;
                    float* hi = hw + HW_ELEMS;
                    int n = l*3;
                    for (int i = tid; i < n; i += 512) hw[i] = 0.f;
                    for (int i = tid; i < n; i += 512) hi[i] = -1.f;
                }
            }
        }
        return;
    }

    // ---- span chunk ----
    int chunk = yb;
    extern __shared__ float sm[];
    float* x_sm = sm;                 // [96][132]
    float* E_sm = sm + LL*XPITCH;     // [96]
    float* M2   = E_sm + LL;          // [192]

    const float* gx = x + ((size_t)b*DD + (size_t)chunk*CHUNK)*LL;
    for (int i = tid; i < CHUNK*LL; i += 512) {
        int d = i / LL;
        int t = i - d*LL;
        x_sm[t*XPITCH + d] = gx[i];
    }
    for (int k = tid; k < 191; k += 512) {
        float denom = __fadd_rn(1.0f, 0.5f*(float)k);
        M2[k] = expf(__fdiv_rn(0.5f, denom) / 0.7f);
    }
    if (tid < LL) E_sm[tid] = g_E[b*LL + tid];
    __syncthreads();

    int wid = tid >> 5, lane = tid & 31;
    int u = g*16 + wid;                     // [0,96)

    run_chain(x_sm, E_sm, M2, out, b, u, chunk, lane);
    if (u < 95)
        run_chain(x_sm, E_sm, M2, out, b, 96 + u, chunk, lane);
}

// ---------------------------------------------------------------------------
extern "C" void kernel_launch(void* const* d_in, const int* in_sizes, int n_in,
                              void* d_out, int out_size) {
    const float* x  = (const float*)d_in[0];
    const int* par  = (const int*)d_in[1];
    const int* pos  = (const int*)d_in[2];
    const int* dep  = (const int*)d_in[3];
    float* out = (float*)d_out;

    int write_aux = (out_size >= SOFT_ELEMS + 2*HW_ELEMS) ? 1 : 0;

    prep_kernel<<<dim3(96, BB), 256>>>(x, par, pos, dep);

    int smem = SPAN_SMEM_FLOATS * 4;
    cudaFuncSetAttribute(span_kernel, cudaFuncAttributeMaxDynamicSharedMemorySize, smem);
    span_kernel<<<dim3(6, NCHUNK + 3, BB), 512, smem>>>(x, out, write_aux);
}